// round 14
// baseline (speedup 1.0000x reference)
#include <cuda_runtime.h>

#define TPB 128
#define PPT 2          // points per thread
#define CHUNK 64       // staging chunk (points) per TMA store

// softplus(x) = max(x,0) + log1p(exp(-|x|)), log1p via degree-4 polynomial on
// e in (0,1] (abs err ~7e-5). One MUFU.EX2 per value.
__device__ __forceinline__ float softplus_p(float x) {
    float e = __expf(-fabsf(x));
    float p = fmaf(-0.0554592f, e, 0.2186653f);
    p = fmaf(p, e, -0.4664423f);
    p = fmaf(p, e, 0.9962620f);
    p = fmaf(p, e, 0.0000695f);
    return fmaxf(x, 0.0f) + p;
}

// Scalar weight SMEM layout (floats):
//   [0..64)    W_in padded 8x8 (cols 6,7 = 0)
//   [64..72)   b_in
//   [72+l*72)  W{1..4} 8x8 + 8 bias, l=0..3
//   [360..480) W_out 15x8
//   [480..495) b_out
__global__ __launch_bounds__(TPB, 8)
void poisson_bivector_kernel(
    const float* __restrict__ x,
    const float* __restrict__ Win, const float* __restrict__ bin,
    const float* __restrict__ W1,  const float* __restrict__ b1,
    const float* __restrict__ W2,  const float* __restrict__ b2,
    const float* __restrict__ W3,  const float* __restrict__ b3,
    const float* __restrict__ W4,  const float* __restrict__ b4,
    const float* __restrict__ Wout,const float* __restrict__ bout,
    float* __restrict__ out, int npts)
{
    __shared__ __align__(16) float s_w[496];
    __shared__ __align__(16) float s_o[2][CHUNK * 36];   // 2 x 9 KB staging

    const int t = threadIdx.x;
    const int base = blockIdx.x * (TPB * PPT);

    // ---- stage weights ----
    for (int i = t; i < 64; i += TPB) {
        int r = i >> 3, c = i & 7;
        s_w[i] = (c < 6) ? Win[r * 6 + c] : 0.0f;
    }
    if (t < 8)  s_w[64 + t]  = bin[t];
    {
        const float* Ws[4] = {W1, W2, W3, W4};
        const float* Bs[4] = {b1, b2, b3, b4};
#pragma unroll
        for (int l = 0; l < 4; l++) {
            int wb = 72 + l * 72;
            for (int i = t; i < 64; i += TPB) s_w[wb + i] = Ws[l][i];
            if (t < 8) s_w[wb + 64 + t] = Bs[l][t];
        }
    }
    for (int i = t; i < 120; i += TPB) s_w[360 + i] = Wout[i];
    if (t < 15) s_w[480 + t] = bout[t];
    __syncthreads();

    // ---- load x for both points ----
    float a[PPT][8];
#pragma unroll
    for (int g = 0; g < PPT; g++) {
        int pt = base + g * TPB + t;
        if (pt < npts) {
            const float2* xp = (const float2*)(x + (size_t)pt * 6);
            float2 v0 = xp[0], v1 = xp[1], v2 = xp[2];
            a[g][0] = v0.x; a[g][1] = v0.y; a[g][2] = v1.x;
            a[g][3] = v1.y; a[g][4] = v2.x; a[g][5] = v2.y;
        } else {
            a[g][0] = a[g][1] = a[g][2] = a[g][3] = a[g][4] = a[g][5] = 0.0f;
        }
        a[g][6] = 0.0f; a[g][7] = 0.0f;
    }

    // ---- 5 hidden layers, weight LDS shared across both points ----
    const int woff[5] = {0, 72, 144, 216, 288};
    const int boff[5] = {64, 136, 208, 280, 352};
#pragma unroll
    for (int l = 0; l < 5; l++) {
        const float4* W = (const float4*)(s_w + woff[l]);
        const float*  b = s_w + boff[l];
        float na[PPT][8];
#pragma unroll
        for (int o = 0; o < 8; o++) {
            float4 w0 = W[2 * o], w1 = W[2 * o + 1];
            float bo = b[o];
#pragma unroll
            for (int g = 0; g < PPT; g++) {
                float acc = bo;
                acc = fmaf(w0.x, a[g][0], acc); acc = fmaf(w0.y, a[g][1], acc);
                acc = fmaf(w0.z, a[g][2], acc); acc = fmaf(w0.w, a[g][3], acc);
                acc = fmaf(w1.x, a[g][4], acc); acc = fmaf(w1.y, a[g][5], acc);
                acc = fmaf(w1.z, a[g][6], acc); acc = fmaf(w1.w, a[g][7], acc);
                na[g][o] = softplus_p(acc);
            }
        }
#pragma unroll
        for (int g = 0; g < PPT; g++)
#pragma unroll
            for (int o = 0; o < 8; o++) a[g][o] = na[g][o];
    }

    // ---- per point-group: output layer, then 2-phase 64-pt staged TMA copyout ----
#pragma unroll
    for (int g = 0; g < PPT; g++) {
        float u[15];
        {
            const float4* W = (const float4*)(s_w + 360);
            const float*  b = s_w + 480;
#pragma unroll
            for (int o = 0; o < 15; o++) {
                float4 w0 = W[2 * o], w1 = W[2 * o + 1];
                float acc = b[o];
                acc = fmaf(w0.x, a[g][0], acc); acc = fmaf(w0.y, a[g][1], acc);
                acc = fmaf(w0.z, a[g][2], acc); acc = fmaf(w0.w, a[g][3], acc);
                acc = fmaf(w1.x, a[g][4], acc); acc = fmaf(w1.y, a[g][5], acc);
                acc = fmaf(w1.z, a[g][6], acc); acc = fmaf(w1.w, a[g][7], acc);
                u[o] = acc;
            }
        }

#pragma unroll
        for (int h = 0; h < 2; h++) {              // phase: threads [h*64, h*64+64) own the chunk
            const int c = g * 2 + h;               // chunk index 0..3
            const int bufi = c & 1;

            if (c >= 2 && t == 0) {
                // buffer reuse: prior TMA store from this buffer must have read SMEM
                asm volatile("cp.async.bulk.wait_group.read 1;" ::: "memory");
            }
            __syncthreads();

            if ((t >> 6) == h) {
                int l = t & 63;
                // 6x6 antisymmetric matrix as 9 float4s (stride 36: conflict-free STS.128)
                float4* so = (float4*)(s_o[bufi] + l * 36);
                so[0] = make_float4( 0.0f,  u[0],   u[1],   u[2]);
                so[1] = make_float4( u[3],  u[4],  -u[0],   0.0f);
                so[2] = make_float4( u[5],  u[6],   u[7],   u[8]);
                so[3] = make_float4(-u[1], -u[5],   0.0f,   u[9]);
                so[4] = make_float4( u[10], u[11], -u[2],  -u[6]);
                so[5] = make_float4(-u[9],  0.0f,   u[12],  u[13]);
                so[6] = make_float4(-u[3], -u[7],  -u[10], -u[12]);
                so[7] = make_float4( 0.0f,  u[14], -u[4],  -u[8]);
                so[8] = make_float4(-u[11],-u[13], -u[14],  0.0f);
            }
            __syncthreads();

            int gb = base + g * TPB + h * CHUNK;
            int cg = npts - gb;
            if (cg > CHUNK) cg = CHUNK;
            if (t == 0 && cg > 0) {
                asm volatile("fence.proxy.async.shared::cta;" ::: "memory");
                unsigned saddr = (unsigned)__cvta_generic_to_shared(s_o[bufi]);
                asm volatile(
                    "cp.async.bulk.global.shared::cta.bulk_group [%0], [%1], %2;"
                    :: "l"(out + (size_t)gb * 36), "r"(saddr), "r"(cg * 144)
                    : "memory");
                asm volatile("cp.async.bulk.commit_group;" ::: "memory");
            }
        }
    }

    // flush outstanding bulk stores before exit
    if (t == 0) {
        asm volatile("cp.async.bulk.wait_group 0;" ::: "memory");
    }
}

extern "C" void kernel_launch(void* const* d_in, const int* in_sizes, int n_in,
                              void* d_out, int out_size) {
    const float* x    = (const float*)d_in[0];
    const float* Win  = (const float*)d_in[1];
    const float* bin  = (const float*)d_in[2];
    const float* W1   = (const float*)d_in[3];
    const float* b1   = (const float*)d_in[4];
    const float* W2   = (const float*)d_in[5];
    const float* b2   = (const float*)d_in[6];
    const float* W3   = (const float*)d_in[7];
    const float* b3   = (const float*)d_in[8];
    const float* W4   = (const float*)d_in[9];
    const float* b4   = (const float*)d_in[10];
    const float* Wout = (const float*)d_in[11];
    const float* bout = (const float*)d_in[12];
    float* out = (float*)d_out;

    int npts = in_sizes[0] / 6;
    int ptsPerBlock = TPB * PPT;
    int blocks = (npts + ptsPerBlock - 1) / ptsPerBlock;
    poisson_bivector_kernel<<<blocks, TPB>>>(
        x, Win, bin, W1, b1, W2, b2, W3, b3, W4, b4, Wout, bout, out, npts);
}